// round 10
// baseline (speedup 1.0000x reference)
#include <cuda_runtime.h>
#include <cstdint>

#define IN_DIM 128
#define W_DIM 160
#define OUT_DIM 224
#define MAX_NODES 50048
#define MAX_EDGES 800000
#define SCAN_BS 256
#define MAX_SCAN_BLOCKS 256

__device__ int g_count[MAX_NODES];
__device__ int g_start[MAX_NODES];
__device__ int g_cursor[MAX_NODES];
__device__ int g_blocksum[MAX_SCAN_BLOCKS];
__device__ int g_perm[MAX_EDGES];

// ---------- preprocessing ----------

__global__ void zero_count_kernel(int n_nodes) {
    int i = blockIdx.x * blockDim.x + threadIdx.x;
    if (i < n_nodes) g_count[i] = 0;
}

__global__ void hist_kernel(const int2* __restrict__ eidx, int n_edges) {
    int i = blockIdx.x * blockDim.x + threadIdx.x;
    if (i < n_edges) atomicAdd(&g_count[__ldcs(&eidx[i]).y], 1);
}

// Stage 1: per-block exclusive scan of counts; writes local prefix to g_start,
// block total to g_blocksum.
__global__ void scan1_kernel(int n_nodes) {
    __shared__ int sm[SCAN_BS];
    int i = blockIdx.x * SCAN_BS + threadIdx.x;
    int v = (i < n_nodes) ? g_count[i] : 0;
    sm[threadIdx.x] = v;
    __syncthreads();
    #pragma unroll
    for (int off = 1; off < SCAN_BS; off <<= 1) {
        int t = (threadIdx.x >= off) ? sm[threadIdx.x - off] : 0;
        __syncthreads();
        sm[threadIdx.x] += t;
        __syncthreads();
    }
    if (i < n_nodes) g_start[i] = sm[threadIdx.x] - v;  // exclusive
    if (threadIdx.x == SCAN_BS - 1) g_blocksum[blockIdx.x] = sm[threadIdx.x];
}

// Stage 2: exclusive scan of block sums (single block).
__global__ void scan2_kernel(int n_blocks) {
    __shared__ int sm[MAX_SCAN_BLOCKS];
    int v = (threadIdx.x < n_blocks) ? g_blocksum[threadIdx.x] : 0;
    sm[threadIdx.x] = v;
    __syncthreads();
    #pragma unroll
    for (int off = 1; off < MAX_SCAN_BLOCKS; off <<= 1) {
        int t = (threadIdx.x >= off) ? sm[threadIdx.x - off] : 0;
        __syncthreads();
        sm[threadIdx.x] += t;
        __syncthreads();
    }
    if (threadIdx.x < n_blocks) g_blocksum[threadIdx.x] = sm[threadIdx.x] - v;
}

// Stage 3: add block offsets; init cursor = start.
__global__ void scan3_kernel(int n_nodes) {
    int i = blockIdx.x * SCAN_BS + threadIdx.x;
    if (i < n_nodes) {
        int s = g_start[i] + g_blocksum[blockIdx.x];
        g_start[i] = s;
        g_cursor[i] = s;
    }
}

__global__ void scatter_kernel(const int2* __restrict__ eidx, int n_edges) {
    int i = blockIdx.x * blockDim.x + threadIdx.x;
    if (i < n_edges) {
        int dst = __ldcs(&eidx[i]).y;
        int pos = atomicAdd(&g_cursor[dst], 1);
        g_perm[pos] = i;
    }
}

// ---------- main kernel: one node per 8-thread group, NO output atomics ----------

__global__ __launch_bounds__(256) void conv_node_kernel(
    const float* __restrict__ nf,        // [n_nodes, 128]
    const float4* __restrict__ ang,      // [n_edges, 4]
    const int2* __restrict__ eidx,       // [n_edges, 2]
    const float* __restrict__ tp,        // [n_edges, 160]
    float* __restrict__ out,             // [n_nodes, 224]
    int n_nodes)
{
    const float INV_SQRT3 = 0.5773502691896258f;
    const float INV_SQRT2 = 0.7071067811865476f;

    int tid = blockIdx.x * 256 + threadIdx.x;
    int node = tid >> 3;
    int g = tid & 7;           // channel group: channels 4g..4g+3
    if (node >= n_nodes) return;

    int start = g_start[node];
    int cnt = g_count[node];

    float4 acc[7];
    #pragma unroll
    for (int s = 0; s < 7; s++) acc[s] = make_float4(0.f, 0.f, 0.f, 0.f);

    int p_next = (cnt > 0) ? __ldg(&g_perm[start]) : 0;

    for (int k = 0; k < cnt; k++) {
        int p = p_next;
        if (k + 1 < cnt) p_next = __ldg(&g_perm[start + k + 1]);

        int src = __ldg(&eidx[p]).x;          // dst == node by construction
        float4 y = __ldcs(&ang[p]);
        float y0 = y.x, yx = y.y, yy = y.z, yz = y.w;

        const float4* hb = (const float4*)(nf + (size_t)src * IN_DIM);
        float4 h0v  = __ldg(&hb[g]);
        float4 h1xv = __ldg(&hb[8 + g]);
        float4 h1yv = __ldg(&hb[16 + g]);
        float4 h1zv = __ldg(&hb[24 + g]);

        const float4* wb = (const float4*)(tp + (size_t)p * W_DIM);
        float4 w0v = __ldcs(&wb[g]);
        float4 w1v = __ldcs(&wb[8 + g]);
        float4 w2v = __ldcs(&wb[16 + g]);
        float4 w3v = __ldcs(&wb[24 + g]);
        float4 w4v = __ldcs(&wb[32 + g]);

        const float* h0p  = (const float*)&h0v;
        const float* h1xp = (const float*)&h1xv;
        const float* h1yp = (const float*)&h1yv;
        const float* h1zp = (const float*)&h1zv;
        const float* w0p  = (const float*)&w0v;
        const float* w1p  = (const float*)&w1v;
        const float* w2p  = (const float*)&w2v;
        const float* w3p  = (const float*)&w3v;
        const float* w4p  = (const float*)&w4v;
        float* a0 = (float*)&acc[0];
        float* a1 = (float*)&acc[1];
        float* a2 = (float*)&acc[2];
        float* a3 = (float*)&acc[3];
        float* a4 = (float*)&acc[4];
        float* a5 = (float*)&acc[5];
        float* a6 = (float*)&acc[6];

        #pragma unroll
        for (int c = 0; c < 4; c++) {
            float H0 = h0p[c], Hx = h1xp[c], Hy = h1yp[c], Hz = h1zp[c];
            float W0 = w0p[c], W1 = w1p[c], W2 = w2p[c], W3 = w3p[c], W4 = w4p[c];

            float dot = Hx * yx + Hy * yy + Hz * yz;
            a0[c] += W0 * (H0 * y0) + (W3 * INV_SQRT3) * dot;

            float a = W1 * H0;
            float b = W2 * y0;
            a1[c] += a * yx + b * Hx;
            a2[c] += a * yy + b * Hy;
            a3[c] += a * yz + b * Hz;

            float s = W4 * INV_SQRT2;
            a4[c] += s * (Hy * yz - Hz * yy);
            a5[c] += s * (Hz * yx - Hx * yz);
            a6[c] += s * (Hx * yy - Hy * yx);
        }
    }

    // Exactly one writer per node: plain coalesced stores (also covers degree-0
    // nodes with zeros, so no separate zero-fill pass is needed).
    float4* ob = (float4*)(out + (size_t)node * OUT_DIM + 4 * g);
    #pragma unroll
    for (int s = 0; s < 7; s++) ob[s * 8] = acc[s];
}

extern "C" void kernel_launch(void* const* d_in, const int* in_sizes, int n_in,
                              void* d_out, int out_size) {
    const float*  nf   = (const float*)d_in[0];      // node_features [n,128]
    const float4* ang  = (const float4*)d_in[1];     // edge_angular  [E,4]
    const int2*   eidx = (const int2*)d_in[2];       // edge_index    [E,2] int32
    const float*  tp   = (const float*)d_in[3];      // tp_weights    [E,160]
    float*        out  = (float*)d_out;

    int n_edges = in_sizes[1] / 4;
    int n_nodes = in_sizes[0] / IN_DIM;

    int scan_blocks = (n_nodes + SCAN_BS - 1) / SCAN_BS;

    zero_count_kernel<<<(n_nodes + 255) / 256, 256>>>(n_nodes);
    hist_kernel<<<(n_edges + 255) / 256, 256>>>(eidx, n_edges);
    scan1_kernel<<<scan_blocks, SCAN_BS>>>(n_nodes);
    scan2_kernel<<<1, MAX_SCAN_BLOCKS>>>(scan_blocks);
    scan3_kernel<<<scan_blocks, SCAN_BS>>>(n_nodes);
    scatter_kernel<<<(n_edges + 255) / 256, 256>>>(eidx, n_edges);

    int total_threads = n_nodes * 8;
    int blocks = (total_threads + 255) / 256;
    conv_node_kernel<<<blocks, 256>>>(nf, ang, eidx, tp, out, n_nodes);
}

// round 11
// speedup vs baseline: 1.4741x; 1.4741x over previous
#include <cuda_runtime.h>
#include <cstdint>

#define IN_DIM 128
#define W_DIM 160
#define OUT_DIM 224
#define MAX_NODES 50048
#define MAX_EDGES 800000
#define SCAN_BS 256
#define MAX_SCAN_BLOCKS 256
#define EPT 16            // sorted edges per 8-thread group

__device__ int g_count[MAX_NODES];
__device__ int g_start[MAX_NODES];
__device__ int g_cursor[MAX_NODES];
__device__ int g_blocksum[MAX_SCAN_BLOCKS];
__device__ int g_perm[MAX_EDGES];

__device__ __forceinline__ void red_add_v4(float* addr, float a, float b, float c, float d) {
    asm volatile("red.global.add.v4.f32 [%0], {%1, %2, %3, %4};"
                 :: "l"(addr), "f"(a), "f"(b), "f"(c), "f"(d)
                 : "memory");
}

// ---------- preprocessing ----------

// Fused: zero output + zero histogram counters (disjoint writes, no race).
__global__ void zero_all_kernel(float4* __restrict__ out, int n4, int n_nodes) {
    int i = blockIdx.x * blockDim.x + threadIdx.x;
    if (i < n4) out[i] = make_float4(0.f, 0.f, 0.f, 0.f);
    if (i < n_nodes) g_count[i] = 0;
}

__global__ void hist_kernel(const int2* __restrict__ eidx, int n_edges) {
    int i = blockIdx.x * blockDim.x + threadIdx.x;
    if (i < n_edges) atomicAdd(&g_count[__ldg(&eidx[i]).y], 1);
}

__global__ void scan1_kernel(int n_nodes) {
    __shared__ int sm[SCAN_BS];
    int i = blockIdx.x * SCAN_BS + threadIdx.x;
    int v = (i < n_nodes) ? g_count[i] : 0;
    sm[threadIdx.x] = v;
    __syncthreads();
    #pragma unroll
    for (int off = 1; off < SCAN_BS; off <<= 1) {
        int t = (threadIdx.x >= off) ? sm[threadIdx.x - off] : 0;
        __syncthreads();
        sm[threadIdx.x] += t;
        __syncthreads();
    }
    if (i < n_nodes) g_start[i] = sm[threadIdx.x] - v;  // exclusive
    if (threadIdx.x == SCAN_BS - 1) g_blocksum[blockIdx.x] = sm[threadIdx.x];
}

__global__ void scan2_kernel(int n_blocks) {
    __shared__ int sm[MAX_SCAN_BLOCKS];
    int v = (threadIdx.x < n_blocks) ? g_blocksum[threadIdx.x] : 0;
    sm[threadIdx.x] = v;
    __syncthreads();
    #pragma unroll
    for (int off = 1; off < MAX_SCAN_BLOCKS; off <<= 1) {
        int t = (threadIdx.x >= off) ? sm[threadIdx.x - off] : 0;
        __syncthreads();
        sm[threadIdx.x] += t;
        __syncthreads();
    }
    if (threadIdx.x < n_blocks) g_blocksum[threadIdx.x] = sm[threadIdx.x] - v;
}

__global__ void scan3_kernel(int n_nodes) {
    int i = blockIdx.x * SCAN_BS + threadIdx.x;
    if (i < n_nodes) {
        int s = g_start[i] + g_blocksum[blockIdx.x];
        g_start[i] = s;
        g_cursor[i] = s;
    }
}

__global__ void scatter_kernel(const int2* __restrict__ eidx, int n_edges) {
    int i = blockIdx.x * blockDim.x + threadIdx.x;
    if (i < n_edges) {
        int dst = __ldg(&eidx[i]).y;
        int pos = atomicAdd(&g_cursor[dst], 1);
        g_perm[pos] = i;
    }
}

// ---------- main: edge-chunked over dst-sorted order, register combining ----------

__device__ __forceinline__ void flush_acc(float* __restrict__ out, int dst, int g,
                                          const float4* acc) {
    float* ob = out + (size_t)dst * OUT_DIM + 4 * g;
    #pragma unroll
    for (int s = 0; s < 7; s++)
        red_add_v4(ob + 32 * s, acc[s].x, acc[s].y, acc[s].z, acc[s].w);
}

__global__ __launch_bounds__(256) void conv_main_kernel(
    const float* __restrict__ nf,        // [n_nodes, 128]
    const float4* __restrict__ ang,      // [n_edges, 4]
    const int2* __restrict__ eidx,       // [n_edges, 2]
    const float* __restrict__ tp,        // [n_edges, 160]
    float* __restrict__ out,             // [n_nodes, 224]
    int n_edges)
{
    const float INV_SQRT3 = 0.5773502691896258f;
    const float INV_SQRT2 = 0.7071067811865476f;

    int tid = blockIdx.x * 256 + threadIdx.x;
    int group = tid >> 3;
    int g = tid & 7;
    int base = group * EPT;
    if (base >= n_edges) return;

    float4 acc[7];
    #pragma unroll
    for (int s = 0; s < 7; s++) acc[s] = make_float4(0.f, 0.f, 0.f, 0.f);
    int cur_dst = -1;

    int p_next = __ldg(&g_perm[base]);
    int2 se_next = __ldg(&eidx[p_next]);

    #pragma unroll 4
    for (int k = 0; k < EPT; k++) {
        int i = base + k;
        if (i >= n_edges) break;
        int p = p_next;
        int2 se = se_next;
        if (i + 1 < n_edges && k + 1 < EPT) {
            p_next = __ldg(&g_perm[i + 1]);
            se_next = __ldg(&eidx[p_next]);
        }

        if (se.y != cur_dst) {
            if (cur_dst >= 0) {
                flush_acc(out, cur_dst, g, acc);
                #pragma unroll
                for (int s = 0; s < 7; s++) acc[s] = make_float4(0.f, 0.f, 0.f, 0.f);
            }
            cur_dst = se.y;
        }

        float4 y = __ldcs(&ang[p]);
        float y0 = y.x, yx = y.y, yy = y.z, yz = y.w;

        const float4* hb = (const float4*)(nf + (size_t)se.x * IN_DIM);
        float4 h0v  = __ldg(&hb[g]);
        float4 h1xv = __ldg(&hb[8 + g]);
        float4 h1yv = __ldg(&hb[16 + g]);
        float4 h1zv = __ldg(&hb[24 + g]);

        const float4* wb = (const float4*)(tp + (size_t)p * W_DIM);
        float4 w0v = __ldcs(&wb[g]);
        float4 w1v = __ldcs(&wb[8 + g]);
        float4 w2v = __ldcs(&wb[16 + g]);
        float4 w3v = __ldcs(&wb[24 + g]);
        float4 w4v = __ldcs(&wb[32 + g]);

        const float* h0p  = (const float*)&h0v;
        const float* h1xp = (const float*)&h1xv;
        const float* h1yp = (const float*)&h1yv;
        const float* h1zp = (const float*)&h1zv;
        const float* w0p  = (const float*)&w0v;
        const float* w1p  = (const float*)&w1v;
        const float* w2p  = (const float*)&w2v;
        const float* w3p  = (const float*)&w3v;
        const float* w4p  = (const float*)&w4v;
        float* a0 = (float*)&acc[0];
        float* a1 = (float*)&acc[1];
        float* a2 = (float*)&acc[2];
        float* a3 = (float*)&acc[3];
        float* a4 = (float*)&acc[4];
        float* a5 = (float*)&acc[5];
        float* a6 = (float*)&acc[6];

        #pragma unroll
        for (int c = 0; c < 4; c++) {
            float H0 = h0p[c], Hx = h1xp[c], Hy = h1yp[c], Hz = h1zp[c];
            float W0 = w0p[c], W1 = w1p[c], W2 = w2p[c], W3 = w3p[c], W4 = w4p[c];

            float dot = Hx * yx + Hy * yy + Hz * yz;
            a0[c] += W0 * (H0 * y0) + (W3 * INV_SQRT3) * dot;

            float a = W1 * H0;
            float b = W2 * y0;
            a1[c] += a * yx + b * Hx;
            a2[c] += a * yy + b * Hy;
            a3[c] += a * yz + b * Hz;

            float s = W4 * INV_SQRT2;
            a4[c] += s * (Hy * yz - Hz * yy);
            a5[c] += s * (Hz * yx - Hx * yz);
            a6[c] += s * (Hx * yy - Hy * yx);
        }
    }

    if (cur_dst >= 0) flush_acc(out, cur_dst, g, acc);
}

extern "C" void kernel_launch(void* const* d_in, const int* in_sizes, int n_in,
                              void* d_out, int out_size) {
    const float*  nf   = (const float*)d_in[0];      // node_features [n,128]
    const float4* ang  = (const float4*)d_in[1];     // edge_angular  [E,4]
    const int2*   eidx = (const int2*)d_in[2];       // edge_index    [E,2] int32
    const float*  tp   = (const float*)d_in[3];      // tp_weights    [E,160]
    float*        out  = (float*)d_out;

    int n_edges = in_sizes[1] / 4;
    int n_nodes = in_sizes[0] / IN_DIM;
    int n4 = out_size / 4;

    int scan_blocks = (n_nodes + SCAN_BS - 1) / SCAN_BS;

    int zmax = (n4 > n_nodes) ? n4 : n_nodes;
    zero_all_kernel<<<(zmax + 255) / 256, 256>>>((float4*)d_out, n4, n_nodes);
    hist_kernel<<<(n_edges + 255) / 256, 256>>>(eidx, n_edges);
    scan1_kernel<<<scan_blocks, SCAN_BS>>>(n_nodes);
    scan2_kernel<<<1, MAX_SCAN_BLOCKS>>>(scan_blocks);
    scan3_kernel<<<scan_blocks, SCAN_BS>>>(n_nodes);
    scatter_kernel<<<(n_edges + 255) / 256, 256>>>(eidx, n_edges);

    int groups = (n_edges + EPT - 1) / EPT;
    int total_threads = groups * 8;
    int blocks = (total_threads + 255) / 256;
    conv_main_kernel<<<blocks, 256>>>(nf, ang, eidx, tp, out, n_edges);
}